// round 17
// baseline (speedup 1.0000x reference)
#include <cuda_runtime.h>

// out[b,t,c] = (1/(t+1)) * sum_{s<=t} x[b,s,c]
// Single-pass decoupled-lookback scan over T.
// Each block owns one (b, chunk of 32 T-rows):
//   1. stream chunk from DRAM -> chunk aggregate (fills L2)
//   2. publish aggregate (threadfence + flag)
//   3. lookback: wait for + sum all predecessor chunk aggregates (L2-resident)
//   4. re-read own chunk (L2 hot) -> running scan -> __stcs to out
// Deadlock-free: 512 blocks, launch_bounds(256,4) caps regs at 64 =>
// capacity 4*148=592 >= 512, all blocks co-resident in wave 1.

#define BB 4
#define TT 4096
#define CC 1024
#define C4 (CC / 4)              // 256 float4 columns = threads per block
#define NCHUNK 128
#define CHUNK_T (TT / NCHUNK)    // 32
#define NTH 256
#define BATCH 8

// Per-(b,chunk) aggregates over all columns: 4*128*256*16B = 2 MB.
__device__ float4 g_agg[BB * NCHUNK * C4];
// Publication flags, zeroed by init kernel each launch (graph-replay safe).
__device__ volatile int g_flags[BB * NCHUNK];

__global__ void __launch_bounds__(NTH)
init_flags() {
    g_flags[blockIdx.x * NTH + threadIdx.x] = 0;   // 2*256 = 512 flags
}

__global__ void __launch_bounds__(NTH, 4)
scan_fused(const float* __restrict__ x, float* __restrict__ out) {
    const int c4    = threadIdx.x;
    const int chunk = blockIdx.y;
    const int b     = blockIdx.z;

    const size_t base = ((size_t)b * TT + (size_t)chunk * CHUNK_T) * CC;
    const float4* __restrict__ p = (const float4*)(x + base) + c4;
    float4*       __restrict__ q = (float4*)(out + base) + c4;

    // ── 1. Local chunk aggregate (streams chunk into L2) ──
    float4 a0 = make_float4(0.f, 0.f, 0.f, 0.f);
    float4 a1 = make_float4(0.f, 0.f, 0.f, 0.f);
#pragma unroll
    for (int batch = 0; batch < CHUNK_T / BATCH; ++batch) {
        float4 buf[BATCH];
#pragma unroll
        for (int i = 0; i < BATCH; ++i)
            buf[i] = p[(size_t)(batch * BATCH + i) * C4];
#pragma unroll
        for (int i = 0; i < BATCH; i += 2) {
            a0.x += buf[i].x;   a0.y += buf[i].y;   a0.z += buf[i].z;   a0.w += buf[i].w;
            a1.x += buf[i+1].x; a1.y += buf[i+1].y; a1.z += buf[i+1].z; a1.w += buf[i+1].w;
        }
    }
    float4 agg;
    agg.x = a0.x + a1.x; agg.y = a0.y + a1.y; agg.z = a0.z + a1.z; agg.w = a0.w + a1.w;

    // ── 2. Publish aggregate ──
    g_agg[(b * NCHUNK + chunk) * C4 + c4] = agg;
    __threadfence();
    __syncthreads();
    if (threadIdx.x == 0)
        g_flags[b * NCHUNK + chunk] = 1;

    // ── 3. Lookback: wait for + sum all predecessor aggregates ──
    float4 off = make_float4(0.f, 0.f, 0.f, 0.f);
    if (chunk > 0) {
        if (threadIdx.x < chunk) {          // distributed wait, one flag per thread
            while (g_flags[b * NCHUNK + threadIdx.x] == 0)
                __nanosleep(64);
        }
        __threadfence();
        __syncthreads();

        const float4* __restrict__ ag = &g_agg[b * NCHUNK * C4 + c4];
#pragma unroll 8
        for (int j = 0; j < chunk; ++j) {
            float4 v = ag[(size_t)j * C4];
            off.x += v.x; off.y += v.y; off.z += v.z; off.w += v.w;
        }
    }

    // ── 4. Re-read own chunk (L2 hot) -> running mean -> streaming store ──
    const int t0 = chunk * CHUNK_T;
    float4 acc = off;
#pragma unroll
    for (int batch = 0; batch < CHUNK_T / BATCH; ++batch) {
        float4 buf[BATCH];
#pragma unroll
        for (int i = 0; i < BATCH; ++i)
            buf[i] = __ldcg(&p[(size_t)(batch * BATCH + i) * C4]);   // L2 hit: just read it
#pragma unroll
        for (int i = 0; i < BATCH; ++i) {
            const int t = batch * BATCH + i;
            acc.x += buf[i].x; acc.y += buf[i].y; acc.z += buf[i].z; acc.w += buf[i].w;
            float inv = __fdividef(1.0f, (float)(t0 + t + 1));
            float4 o;
            o.x = acc.x * inv; o.y = acc.y * inv; o.z = acc.z * inv; o.w = acc.w * inv;
            __stcs(&q[(size_t)t * C4], o);   // evict-first write stream
        }
    }
}

extern "C" void kernel_launch(void* const* d_in, const int* in_sizes, int n_in,
                              void* d_out, int out_size) {
    const float* x = (const float*)d_in[0];
    float* out = (float*)d_out;

    init_flags<<<BB * NCHUNK / NTH, NTH>>>();           // 512 flags
    scan_fused<<<dim3(1, NCHUNK, BB), NTH>>>(x, out);   // 512 blocks, all co-resident
}